// round 6
// baseline (speedup 1.0000x reference)
#include <cuda_runtime.h>

// FastGuidedFilterColor: lr_x (8,3,256,256) f32, lr_y (8,3,256,256) f32,
// hr_x (8,3,1024,1024) f32, r=1 -> out (8,3,1024,1024) f32
//
// Replication of the JAX reference with XLA ReduceWindowRewriter blocked-scan
// rounding for cumsum (base_length B=16):
//   S_j   = serial left-fold within 16-elem block (init 0, exact first add)
//   T_k   = full block sum (== S_15)
//   C_k   = serial left-fold of T_0..T_{k-1}   (C_0 = 0)
//   cs[16k+j] = round(C_k + S_j)               (single rounded add)
// All other elementwise math in f32 with explicit non-FMA intrinsics,
// true IEEE divides; bilinear resize = separable clamped lerp, exact
// dyadic weights (== renormalized edge weights).

#define NB 8
#define NC 3
#define LH 256
#define LW 256
#define HH 1024
#define HW 1024
#define EPSV 1e-8f
#define NPL 21   // planes per batch: 3 x, 3 y, 6 xx, 9 xy
#define BLK 16   // xla_reduce_window_rewrite_base_length

// scan buffer (in-place for H pass): [B][21][LH][LW]
__device__ float g_box[NB * NPL * LH * LW];
// A/b planes: [B][12][LH][LW]; plane i*4+{A0,A1,A2,b}
__device__ float g_ab[NB * 12 * LH * LW];

// xx pair tables (I1, I2)
__device__ __constant__ int cI1[6] = {0, 0, 0, 1, 1, 2};
__device__ __constant__ int cI2[6] = {0, 1, 2, 1, 2, 2};

// ---------------------------------------------------------------------------
// Stage A: products + vertical blocked-scan cumsum + vertical diff (r=1)
// thread per (b, plane, x); walks y = 0..255
// ---------------------------------------------------------------------------
__global__ void __launch_bounds__(256) gf_scan_v(
    const float* __restrict__ lrx,
    const float* __restrict__ lry)
{
    int idx = blockIdx.x * blockDim.x + threadIdx.x;
    if (idx >= NB * NPL * LW) return;
    int x = idx % LW;
    int plane = (idx / LW) % NPL;
    int b = idx / (LW * NPL);

    const int pl = LH * LW;
    const float* pA;
    const float* pB = nullptr;
    if (plane < 3) {
        pA = lrx + ((size_t)b * NC + plane) * pl + x;
    } else if (plane < 6) {
        pA = lry + ((size_t)b * NC + (plane - 3)) * pl + x;
    } else if (plane < 12) {
        int k = plane - 6;
        pA = lrx + ((size_t)b * NC + cI1[k]) * pl + x;
        pB = lrx + ((size_t)b * NC + cI2[k]) * pl + x;
    } else {
        int q = plane - 12;
        int i = q / 3;   // y channel
        int c = q % 3;   // x channel
        pA = lrx + ((size_t)b * NC + c) * pl + x;
        pB = lry + ((size_t)b * NC + i) * pl + x;
    }

    float* outp = g_box + ((size_t)b * NPL + plane) * pl + x;

    float carry = 0.f;                    // C_k: serial fold of block totals
    float inner = 0.f;                    // S_j within current block
    float h1 = 0.f, h2 = 0.f, h3 = 0.f;   // cs[t-1], cs[t-2], cs[t-3]

    for (int t = 0; t < LH; t++) {
        float v = pA[t * LW];
        if (pB) v = __fmul_rn(v, pB[t * LW]);

        if ((t & (BLK - 1)) == 0) {
            if (t > 0) carry = __fadd_rn(carry, inner);  // C_{k} += T_{k-1}
            inner = 0.f;
        }
        inner = __fadd_rn(inner, v);                     // S_j serial
        float cs = __fadd_rn(carry, inner);              // single carry add

        // out[i] for i>=2: cs[i+1]-cs[i-2]; out[0]=cs[1], out[1]=cs[2]
        if (t >= 1) {
            float ov = (t >= 3) ? __fsub_rn(cs, h3) : cs;
            outp[(t - 1) * LW] = ov;
        }
        h3 = h2; h2 = h1; h1 = cs;
    }
    // out[255] = cs[255] - cs[253]
    outp[(LH - 1) * LW] = __fsub_rn(h1, h3);
}

// ---------------------------------------------------------------------------
// Stage B: horizontal blocked-scan cumsum + diff, in place on g_box
// thread per (b, plane, y); walks x = 0..255
// ---------------------------------------------------------------------------
__global__ void __launch_bounds__(256) gf_scan_h()
{
    int idx = blockIdx.x * blockDim.x + threadIdx.x;
    if (idx >= NB * NPL * LH) return;
    int y = idx % LH;
    int plane = (idx / LH) % NPL;
    int b = idx / (LH * NPL);

    float* row = g_box + (((size_t)b * NPL + plane) * LH + y) * LW;

    float carry = 0.f;
    float inner = 0.f;
    float h1 = 0.f, h2 = 0.f, h3 = 0.f;

    for (int t = 0; t < LW; t++) {
        float v = row[t];

        if ((t & (BLK - 1)) == 0) {
            if (t > 0) carry = __fadd_rn(carry, inner);
            inner = 0.f;
        }
        inner = __fadd_rn(inner, v);
        float cs = __fadd_rn(carry, inner);

        if (t >= 1) {
            float ov = (t >= 3) ? __fsub_rn(cs, h3) : cs;
            row[t - 1] = ov;  // in-place: write lags read by one, same thread
        }
        h3 = h2; h2 = h1; h1 = cs;
    }
    row[LW - 1] = __fsub_rn(h1, h3);
}

// ---------------------------------------------------------------------------
// Stage C: per-pixel covariance solve -> A (3) and b per output channel
// ---------------------------------------------------------------------------
__global__ void __launch_bounds__(256) gf_solve()
{
    int idx = blockIdx.x * blockDim.x + threadIdx.x;
    if (idx >= NB * LH * LW) return;
    int x = idx % LW;
    int y = (idx / LW) % LH;
    int b = idx / (LW * LH);

    const int pl = LH * LW;
    const float* box = g_box + (size_t)b * NPL * pl + y * LW + x;

    // exact window count (ones-boxfilter gives exact small integers)
    int y0 = max(0, y - 1), y1 = min(LH - 1, y + 1);
    int x0 = max(0, x - 1), x1 = min(LW - 1, x + 1);
    float n = (float)((y1 - y0 + 1) * (x1 - x0 + 1));

    float mx[3], my[3];
    #pragma unroll
    for (int c = 0; c < 3; c++) mx[c] = __fdiv_rn(box[c * pl], n);
    #pragma unroll
    for (int c = 0; c < 3; c++) my[c] = __fdiv_rn(box[(3 + c) * pl], n);

    // var entries [xx, xy, xz, yy, yz, zz]
    float v[6];
    {
        const int i1[6] = {0, 0, 0, 1, 1, 2};
        const int i2[6] = {0, 1, 2, 1, 2, 2};
        #pragma unroll
        for (int k = 0; k < 6; k++) {
            float d = __fdiv_rn(box[(6 + k) * pl], n);
            float mm = __fmul_rn(mx[i1[k]], mx[i2[k]]);
            v[k] = __fadd_rn(__fsub_rn(d, mm), EPSV);
        }
    }

    // cofactors per reference CA/CB/CC/CD tables
    float c0 = __fsub_rn(__fmul_rn(v[3], v[5]), __fmul_rn(v[4], v[4]));
    float c1 = __fsub_rn(__fmul_rn(v[4], v[2]), __fmul_rn(v[1], v[5]));
    float c2 = __fsub_rn(__fmul_rn(v[1], v[4]), __fmul_rn(v[3], v[2]));
    float c3 = __fsub_rn(__fmul_rn(v[0], v[5]), __fmul_rn(v[2], v[2]));
    float c4 = __fsub_rn(__fmul_rn(v[2], v[1]), __fmul_rn(v[0], v[4]));
    float c5 = __fsub_rn(__fmul_rn(v[0], v[3]), __fmul_rn(v[1], v[1]));

    float det = __fadd_rn(__fadd_rn(__fmul_rn(c0, v[0]), __fmul_rn(c1, v[1])),
                          __fmul_rn(c2, v[2]));
    c0 = __fdiv_rn(c0, det);
    c1 = __fdiv_rn(c1, det);
    c2 = __fdiv_rn(c2, det);
    c3 = __fdiv_rn(c3, det);
    c4 = __fdiv_rn(c4, det);
    c5 = __fdiv_rn(c5, det);

    float* outp = g_ab + (size_t)b * 12 * pl + y * LW + x;

    #pragma unroll
    for (int i = 0; i < 3; i++) {
        float cov[3];
        #pragma unroll
        for (int c = 0; c < 3; c++) {
            float d = __fdiv_rn(box[(12 + i * 3 + c) * pl], n);
            cov[c] = __fsub_rn(d, __fmul_rn(mx[c], my[i]));
        }
        float A0 = __fadd_rn(__fadd_rn(__fmul_rn(c0, cov[0]), __fmul_rn(c1, cov[1])),
                             __fmul_rn(c2, cov[2]));
        float A1 = __fadd_rn(__fadd_rn(__fmul_rn(c1, cov[0]), __fmul_rn(c3, cov[1])),
                             __fmul_rn(c4, cov[2]));
        float A2 = __fadd_rn(__fadd_rn(__fmul_rn(c2, cov[0]), __fmul_rn(c4, cov[1])),
                             __fmul_rn(c5, cov[2]));
        float s = __fadd_rn(__fadd_rn(__fmul_rn(A0, mx[0]), __fmul_rn(A1, mx[1])),
                            __fmul_rn(A2, mx[2]));
        float bb = __fsub_rn(my[i], s);
        outp[(i * 4 + 0) * pl] = A0;
        outp[(i * 4 + 1) * pl] = A1;
        outp[(i * 4 + 2) * pl] = A2;
        outp[(i * 4 + 3) * pl] = bb;
    }
}

// ---------------------------------------------------------------------------
// Stage D: bilinear upsample (separable, H then W, clamped == renormalized)
// and apply out = A . hr_x + b
// ---------------------------------------------------------------------------
__global__ void __launch_bounds__(256) gf_apply(
    const float* __restrict__ hrx,
    float* __restrict__ out)
{
    int idx = blockIdx.x * blockDim.x + threadIdx.x;
    if (idx >= NB * HH * HW) return;
    int x = idx % HW;
    int y = (idx / HW) % HH;
    int b = idx / (HW * HH);

    float fy = (y + 0.5f) * 0.25f - 0.5f;   // exact dyadic
    float fx = (x + 0.5f) * 0.25f - 0.5f;
    fy = fminf(fmaxf(fy, 0.0f), (float)(LH - 1));
    fx = fminf(fmaxf(fx, 0.0f), (float)(LW - 1));
    int iy0 = (int)fy;
    int ix0 = (int)fx;
    float wy = fy - (float)iy0;             // exact dyadic
    float wx = fx - (float)ix0;
    int iy1 = min(iy0 + 1, LH - 1);
    int ix1 = min(ix0 + 1, LW - 1);
    float wy0 = 1.0f - wy, wy1 = wy;
    float wx0 = 1.0f - wx, wx1 = wx;

    const int pl = LH * LW;
    const float* ab = g_ab + (size_t)b * 12 * pl;
    int o00 = iy0 * LW + ix0;
    int o01 = iy0 * LW + ix1;
    int o10 = iy1 * LW + ix0;
    int o11 = iy1 * LW + ix1;

    float v[12];
    #pragma unroll
    for (int p = 0; p < 12; p++) {
        const float* q = ab + p * pl;
        // H lerp first (rounded), then W lerp — separable resize order
        float a = __fadd_rn(__fmul_rn(q[o00], wy0), __fmul_rn(q[o10], wy1));
        float c = __fadd_rn(__fmul_rn(q[o01], wy0), __fmul_rn(q[o11], wy1));
        v[p] = __fadd_rn(__fmul_rn(a, wx0), __fmul_rn(c, wx1));
    }

    const int hpl = HH * HW;
    size_t base = ((size_t)b * NC) * hpl + (size_t)y * HW + x;
    float hx0 = hrx[base];
    float hx1 = hrx[base + hpl];
    float hx2 = hrx[base + 2 * hpl];

    #pragma unroll
    for (int i = 0; i < 3; i++) {
        float s = __fadd_rn(__fadd_rn(__fmul_rn(v[i * 4 + 0], hx0),
                                      __fmul_rn(v[i * 4 + 1], hx1)),
                            __fmul_rn(v[i * 4 + 2], hx2));
        out[base + (size_t)i * hpl] = __fadd_rn(s, v[i * 4 + 3]);
    }
}

extern "C" void kernel_launch(void* const* d_in, const int* in_sizes, int n_in,
                              void* d_out, int out_size)
{
    const float* lrx = (const float*)d_in[0];
    const float* lry = (const float*)d_in[1];
    const float* hrx = (const float*)d_in[2];
    float* out = (float*)d_out;

    {
        int total = NB * NPL * LW;                    // 43008
        gf_scan_v<<<(total + 255) / 256, 256>>>(lrx, lry);
    }
    {
        int total = NB * NPL * LH;                    // 43008
        gf_scan_h<<<(total + 255) / 256, 256>>>();
    }
    {
        int total = NB * LH * LW;                     // 524288
        gf_solve<<<(total + 255) / 256, 256>>>();
    }
    {
        int total = NB * HH * HW;                     // 8388608
        gf_apply<<<(total + 255) / 256, 256>>>(hrx, out);
    }
}

// round 7
// speedup vs baseline: 3.3203x; 3.3203x over previous
#include <cuda_runtime.h>

// FastGuidedFilterColor: lr_x (8,3,256,256) f32, lr_y (8,3,256,256) f32,
// hr_x (8,3,1024,1024) f32, r=1 -> out (8,3,1024,1024) f32
//
// Bit-faithful to JAX reference (XLA ReduceWindowRewriter blocked scan, B=16):
//   S_j   = serial left-fold within 16-elem block (init 0, first add exact)
//   C_k   = serial left-fold of block totals T_0..T_{k-1}  (C_0 = 0)
//   cs[16k+j] = round(C_k + S_j)
// Elementwise math uses explicit non-FMA intrinsics + IEEE divides.
// Bilinear resize: separable clamped lerp with exact dyadic weights.

#define NB 8
#define NC 3
#define LH 256
#define LW 256
#define HH 1024
#define HW 1024
#define EPSV 1e-8f
#define NPL 21
#define PL (LH * LW)

// box-filtered planes: [B][21][LH][LW]
__device__ float g_box[NB * NPL * PL];
// A/b pixel-major: [B][LH*LW][12] ; per pixel: ch i -> {A0,A1,A2,b} at 4i..4i+3
__device__ float g_ab2[NB * PL * 12];

__device__ __constant__ int cI1[6] = {0, 0, 0, 1, 1, 2};
__device__ __constant__ int cI2[6] = {0, 1, 2, 1, 2, 2};

// ---------------------------------------------------------------------------
// Kernel 1: fused box filter. Block = one (b, plane) 256x256 image.
//  Phase 1: vertical blocked scan + diff (thread = column), write g_box.
//  Phase 2: horizontal blocked scan + diff in-place, warp-parallel:
//           half-warp lane k owns 16-elem block k; carries via serial shfl fold.
// ---------------------------------------------------------------------------
__global__ void __launch_bounds__(256) gf_box(
    const float* __restrict__ lrx,
    const float* __restrict__ lry)
{
    int blk = blockIdx.x;            // b*NPL + plane
    int plane = blk % NPL;
    int b = blk / NPL;
    int tid = threadIdx.x;

    float* pp = g_box + ((size_t)b * NPL + plane) * PL;

    // ---- Phase 1: vertical (column = tid) ----
    {
        const float* pA;
        const float* pB = nullptr;
        if (plane < 3) {
            pA = lrx + ((size_t)b * NC + plane) * PL + tid;
        } else if (plane < 6) {
            pA = lry + ((size_t)b * NC + (plane - 3)) * PL + tid;
        } else if (plane < 12) {
            int k = plane - 6;
            pA = lrx + ((size_t)b * NC + cI1[k]) * PL + tid;
            pB = lrx + ((size_t)b * NC + cI2[k]) * PL + tid;
        } else {
            int q = plane - 12;
            int i = q / 3;
            int c = q % 3;
            pA = lrx + ((size_t)b * NC + c) * PL + tid;
            pB = lry + ((size_t)b * NC + i) * PL + tid;
        }
        float* outp = pp + tid;

        float carry = 0.f, inner = 0.f;
        float h1 = 0.f, h2 = 0.f, h3 = 0.f;
        for (int t = 0; t < LH; t++) {
            float v = pA[t * LW];
            if (pB) v = __fmul_rn(v, pB[t * LW]);
            if ((t & 15) == 0) {
                if (t > 0) carry = __fadd_rn(carry, inner);
                inner = 0.f;
            }
            inner = __fadd_rn(inner, v);
            float cs = __fadd_rn(carry, inner);
            if (t >= 1) {
                float ov = (t >= 3) ? __fsub_rn(cs, h3) : cs;
                outp[(t - 1) * LW] = ov;
            }
            h3 = h2; h2 = h1; h1 = cs;
        }
        outp[(LH - 1) * LW] = __fsub_rn(h1, h3);
    }
    __syncthreads();

    // ---- Phase 2: horizontal, warp handles 2 rows per pass ----
    int wid = tid >> 5;
    int lane = tid & 31;
    int half = (lane >> 4) & 1;   // 0: row r0, 1: row r1
    int k = lane & 15;            // block index within row

    __shared__ float rowbuf[16][LW];

    for (int pass = 0; pass < 16; pass++) {
        int y = (pass * 8 + wid) * 2 + half;
        const float4* rv = (const float4*)(pp + (size_t)y * LW) + k * 4;
        float4 a0 = rv[0], a1 = rv[1], a2 = rv[2], a3 = rv[3];
        float e[16] = {a0.x, a0.y, a0.z, a0.w,
                       a1.x, a1.y, a1.z, a1.w,
                       a2.x, a2.y, a2.z, a2.w,
                       a3.x, a3.y, a3.z, a3.w};
        float pre[16];
        pre[0] = e[0];  // fadd(0, e0) exact
        #pragma unroll
        for (int j = 1; j < 16; j++) pre[j] = __fadd_rn(pre[j - 1], e[j]);

        float T = pre[15];
        float carry = 0.f;
        #pragma unroll
        for (int i = 0; i < 16; i++) {
            float Ti = __shfl_sync(0xFFFFFFFFu, T, (half << 4) | i);
            if (i < k) carry = __fadd_rn(carry, Ti);   // serial fold order
        }

        float* rb = rowbuf[wid * 2 + half];
        #pragma unroll
        for (int j = 0; j < 16; j++) rb[k * 16 + j] = __fadd_rn(carry, pre[j]);
        __syncwarp();

        #pragma unroll
        for (int h = 0; h < 2; h++) {
            int yy = (pass * 8 + wid) * 2 + h;
            const float* rr = rowbuf[wid * 2 + h];
            float* orow = pp + (size_t)yy * LW;
            #pragma unroll
            for (int j = 0; j < 8; j++) {
                int i = j * 32 + lane;
                float ov;
                if (i == 0)            ov = rr[1];
                else if (i == 1)       ov = rr[2];
                else if (i == LW - 1)  ov = __fsub_rn(rr[LW - 1], rr[LW - 3]);
                else                   ov = __fsub_rn(rr[i + 1], rr[i - 2]);
                orow[i] = ov;
            }
        }
        __syncwarp();
    }
}

// ---------------------------------------------------------------------------
// Kernel 2: per-pixel covariance solve -> pixel-major A/b (float4 stores)
// ---------------------------------------------------------------------------
__global__ void __launch_bounds__(256) gf_solve()
{
    int idx = blockIdx.x * blockDim.x + threadIdx.x;
    if (idx >= NB * PL) return;
    int x = idx % LW;
    int y = (idx / LW) % LH;
    int b = idx / PL;

    const float* box = g_box + (size_t)b * NPL * PL + y * LW + x;

    int y0 = max(0, y - 1), y1 = min(LH - 1, y + 1);
    int x0 = max(0, x - 1), x1 = min(LW - 1, x + 1);
    float n = (float)((y1 - y0 + 1) * (x1 - x0 + 1));

    float mx[3], my[3];
    #pragma unroll
    for (int c = 0; c < 3; c++) mx[c] = __fdiv_rn(box[c * PL], n);
    #pragma unroll
    for (int c = 0; c < 3; c++) my[c] = __fdiv_rn(box[(3 + c) * PL], n);

    float v[6];
    {
        const int i1[6] = {0, 0, 0, 1, 1, 2};
        const int i2[6] = {0, 1, 2, 1, 2, 2};
        #pragma unroll
        for (int k = 0; k < 6; k++) {
            float d = __fdiv_rn(box[(6 + k) * PL], n);
            float mm = __fmul_rn(mx[i1[k]], mx[i2[k]]);
            v[k] = __fadd_rn(__fsub_rn(d, mm), EPSV);
        }
    }

    float c0 = __fsub_rn(__fmul_rn(v[3], v[5]), __fmul_rn(v[4], v[4]));
    float c1 = __fsub_rn(__fmul_rn(v[4], v[2]), __fmul_rn(v[1], v[5]));
    float c2 = __fsub_rn(__fmul_rn(v[1], v[4]), __fmul_rn(v[3], v[2]));
    float c3 = __fsub_rn(__fmul_rn(v[0], v[5]), __fmul_rn(v[2], v[2]));
    float c4 = __fsub_rn(__fmul_rn(v[2], v[1]), __fmul_rn(v[0], v[4]));
    float c5 = __fsub_rn(__fmul_rn(v[0], v[3]), __fmul_rn(v[1], v[1]));

    float det = __fadd_rn(__fadd_rn(__fmul_rn(c0, v[0]), __fmul_rn(c1, v[1])),
                          __fmul_rn(c2, v[2]));
    c0 = __fdiv_rn(c0, det);
    c1 = __fdiv_rn(c1, det);
    c2 = __fdiv_rn(c2, det);
    c3 = __fdiv_rn(c3, det);
    c4 = __fdiv_rn(c4, det);
    c5 = __fdiv_rn(c5, det);

    float4* o4 = (float4*)(g_ab2 + ((size_t)b * PL + (size_t)y * LW + x) * 12);

    #pragma unroll
    for (int i = 0; i < 3; i++) {
        float cov[3];
        #pragma unroll
        for (int c = 0; c < 3; c++) {
            float d = __fdiv_rn(box[(12 + i * 3 + c) * PL], n);
            cov[c] = __fsub_rn(d, __fmul_rn(mx[c], my[i]));
        }
        float A0 = __fadd_rn(__fadd_rn(__fmul_rn(c0, cov[0]), __fmul_rn(c1, cov[1])),
                             __fmul_rn(c2, cov[2]));
        float A1 = __fadd_rn(__fadd_rn(__fmul_rn(c1, cov[0]), __fmul_rn(c3, cov[1])),
                             __fmul_rn(c4, cov[2]));
        float A2 = __fadd_rn(__fadd_rn(__fmul_rn(c2, cov[0]), __fmul_rn(c4, cov[1])),
                             __fmul_rn(c5, cov[2]));
        float s = __fadd_rn(__fadd_rn(__fmul_rn(A0, mx[0]), __fmul_rn(A1, mx[1])),
                            __fmul_rn(A2, mx[2]));
        float bb = __fsub_rn(my[i], s);
        o4[i] = make_float4(A0, A1, A2, bb);
    }
}

// ---------------------------------------------------------------------------
// Kernel 3: bilinear upsample + apply. Thread = 4 consecutive output x.
// Column y-lerps computed once per lr column (bit-identical to per-pixel).
// ---------------------------------------------------------------------------
__global__ void __launch_bounds__(256) gf_apply(
    const float* __restrict__ hrx,
    float* __restrict__ out)
{
    int idx = blockIdx.x * blockDim.x + threadIdx.x;   // NB*HH*256
    int g = idx & 255;                 // output x group: x = 4g..4g+3
    int y = (idx >> 8) & (HH - 1);
    int b = idx >> 18;

    float fy = (y + 0.5f) * 0.25f - 0.5f;
    fy = fminf(fmaxf(fy, 0.0f), (float)(LH - 1));
    int iy0 = (int)fy;
    float wy = fy - (float)iy0;
    int iy1 = min(iy0 + 1, LH - 1);
    float wy0 = 1.0f - wy, wy1 = wy;

    int colA = max(g - 1, 0);
    int colB = g;
    int colC = min(g + 1, LW - 1);

    const float4* ab = (const float4*)g_ab2 + (size_t)b * PL * 3;
    float4 cvA[3], cvB[3], cvC[3];
    {
        int cols[3] = {colA, colB, colC};
        #pragma unroll
        for (int c = 0; c < 3; c++) {
            const float4* top = ab + ((size_t)iy0 * LW + cols[c]) * 3;
            const float4* bot = ab + ((size_t)iy1 * LW + cols[c]) * 3;
            float4* dst = (c == 0) ? cvA : (c == 1) ? cvB : cvC;
            #pragma unroll
            for (int q = 0; q < 3; q++) {
                float4 t = top[q], bo = bot[q];
                float4 r;
                r.x = __fadd_rn(__fmul_rn(t.x, wy0), __fmul_rn(bo.x, wy1));
                r.y = __fadd_rn(__fmul_rn(t.y, wy0), __fmul_rn(bo.y, wy1));
                r.z = __fadd_rn(__fmul_rn(t.z, wy0), __fmul_rn(bo.z, wy1));
                r.w = __fadd_rn(__fmul_rn(t.w, wy0), __fmul_rn(bo.w, wy1));
                dst[q] = r;
            }
        }
    }

    size_t hbase = (((size_t)b * 3) * HH + y) * HW + ((size_t)g << 2);
    const size_t hpl = (size_t)HH * HW;
    float4 hq0 = *(const float4*)(hrx + hbase);
    float4 hq1 = *(const float4*)(hrx + hbase + hpl);
    float4 hq2 = *(const float4*)(hrx + hbase + 2 * hpl);
    float hx0[4] = {hq0.x, hq0.y, hq0.z, hq0.w};
    float hx1[4] = {hq1.x, hq1.y, hq1.z, hq1.w};
    float hx2[4] = {hq2.x, hq2.y, hq2.z, hq2.w};

    float o0[4], o1[4], o2[4];
    #pragma unroll
    for (int d = 0; d < 4; d++) {
        float fx = ((float)(4 * g + d) + 0.5f) * 0.25f - 0.5f;
        fx = fminf(fmaxf(fx, 0.0f), (float)(LW - 1));
        int ix0 = (int)fx;
        float wx = fx - (float)ix0;
        int ix1 = min(ix0 + 1, LW - 1);
        float wx0 = 1.0f - wx, wx1 = wx;
        int i0 = ix0 - g + 1;   // 0 -> colA, 1 -> colB
        int i1 = ix1 - g + 1;   // 1 -> colB, 2 -> colC

        #pragma unroll
        for (int q = 0; q < 3; q++) {
            float4 l = (i0 == 0) ? cvA[q] : cvB[q];
            float4 rr = (i1 == 2) ? cvC[q] : cvB[q];
            float v0 = __fadd_rn(__fmul_rn(l.x, wx0), __fmul_rn(rr.x, wx1));
            float v1 = __fadd_rn(__fmul_rn(l.y, wx0), __fmul_rn(rr.y, wx1));
            float v2 = __fadd_rn(__fmul_rn(l.z, wx0), __fmul_rn(rr.z, wx1));
            float v3 = __fadd_rn(__fmul_rn(l.w, wx0), __fmul_rn(rr.w, wx1));
            float s = __fadd_rn(__fadd_rn(__fmul_rn(v0, hx0[d]),
                                          __fmul_rn(v1, hx1[d])),
                                __fmul_rn(v2, hx2[d]));
            float oo = __fadd_rn(s, v3);
            if (q == 0) o0[d] = oo; else if (q == 1) o1[d] = oo; else o2[d] = oo;
        }
    }

    float* outp = out + hbase;
    *(float4*)outp = make_float4(o0[0], o0[1], o0[2], o0[3]);
    *(float4*)(outp + hpl) = make_float4(o1[0], o1[1], o1[2], o1[3]);
    *(float4*)(outp + 2 * hpl) = make_float4(o2[0], o2[1], o2[2], o2[3]);
}

extern "C" void kernel_launch(void* const* d_in, const int* in_sizes, int n_in,
                              void* d_out, int out_size)
{
    const float* lrx = (const float*)d_in[0];
    const float* lry = (const float*)d_in[1];
    const float* hrx = (const float*)d_in[2];
    float* out = (float*)d_out;

    gf_box<<<NB * NPL, 256>>>(lrx, lry);                       // 168 blocks
    gf_solve<<<(NB * PL + 255) / 256, 256>>>();                // 2048 blocks
    gf_apply<<<(NB * HH * (HW / 4) + 255) / 256, 256>>>(hrx, out); // 8192 blocks
}

// round 8
// speedup vs baseline: 3.5308x; 1.0634x over previous
#include <cuda_runtime.h>

// FastGuidedFilterColor — bit-faithful to JAX reference
// (XLA ReduceWindowRewriter blocked scan, base_length B=16):
//   S_j = serial left-fold within 16-elem block; C_k = serial fold of totals;
//   cs[16k+j] = round(C_k + S_j). Non-FMA intrinsics, IEEE divides.
// Bilinear resize: separable clamped lerp, exact dyadic weights.

#define NB 8
#define NC 3
#define LH 256
#define LW 256
#define HH 1024
#define HW 1024
#define EPSV 1e-8f
#define NPL 21
#define PL (LH * LW)

__device__ float g_box[NB * NPL * PL];
__device__ float g_ab2[NB * PL * 12];   // pixel-major: [b][pix][ch*4 + {A0,A1,A2,b}]

__device__ __constant__ int cI1[6] = {0, 0, 0, 1, 1, 2};
__device__ __constant__ int cI2[6] = {0, 1, 2, 1, 2, 2};

// ---------------------------------------------------------------------------
// Kernel 1: fused box filter. Block = one (b, plane) 256x256 image, 1024 thr.
// Phase 1 (vertical): two-pass blocked scan. Thread = (x, 4 consecutive
//   16-row blocks). Pass A: block totals T + inner[13]/inner[14] partials.
//   Pass B: serial carry fold (identical association) + rescan + diff.
// Phase 2 (horizontal): half-warp per row, lane = 16-elem block, shfl carries.
// ---------------------------------------------------------------------------
__global__ void __launch_bounds__(1024) gf_box(
    const float* __restrict__ lrx,
    const float* __restrict__ lry)
{
    int blk = blockIdx.x;            // b*NPL + plane
    int plane = blk % NPL;
    int b = blk / NPL;
    int tid = threadIdx.x;

    float* pp = g_box + ((size_t)b * NPL + plane) * PL;

    __shared__ float smem_pool[8192];            // 32 KB, reused per phase
    float* Tsm  = smem_pool;                     // [16][256]
    float* i13s = smem_pool + 4096;              // [4][256]  (m==3 blocks)
    float* i14s = smem_pool + 5120;              // [4][256]

    // plane operand pointers
    const float* pA;
    const float* pB = nullptr;
    {
        int x = tid & 255;
        if (plane < 3) {
            pA = lrx + ((size_t)b * NC + plane) * PL + x;
        } else if (plane < 6) {
            pA = lry + ((size_t)b * NC + (plane - 3)) * PL + x;
        } else if (plane < 12) {
            int k = plane - 6;
            pA = lrx + ((size_t)b * NC + cI1[k]) * PL + x;
            pB = lrx + ((size_t)b * NC + cI2[k]) * PL + x;
        } else {
            int q = plane - 12;
            pA = lrx + ((size_t)b * NC + (q % 3)) * PL + x;
            pB = lry + ((size_t)b * NC + (q / 3)) * PL + x;
        }
    }

    // ---- Phase 1, pass A: block totals ----
    int x = tid & 255;
    int g4 = tid >> 8;                 // 0..3 : owns y-blocks 4g4..4g4+3
    float Tloc[4];
    {
        #pragma unroll
        for (int m = 0; m < 4; m++) {
            int base = g4 * 64 + m * 16;
            float inner = 0.f, i13 = 0.f, i14 = 0.f;
            #pragma unroll
            for (int j = 0; j < 16; j++) {
                float v = pA[(base + j) * LW];
                if (pB) v = __fmul_rn(v, pB[(base + j) * LW]);
                inner = __fadd_rn(inner, v);
                if (j == 13) i13 = inner;
                if (j == 14) i14 = inner;
            }
            Tloc[m] = inner;
            Tsm[(g4 * 4 + m) * 256 + x] = inner;
            if (m == 3) {
                i13s[g4 * 256 + x] = i13;
                i14s[g4 * 256 + x] = i14;
            }
        }
    }
    __syncthreads();

    // ---- Phase 1, pass B: carry fold + rescan + vertical diff ----
    {
        float C = 0.f, Cprev = 0.f;
        for (int j = 0; j < g4 * 4; j++) {
            Cprev = C;
            C = __fadd_rn(C, Tsm[j * 256 + x]);    // serial fold order
        }
        float h1 = 0.f, h2 = 0.f, h3 = 0.f;
        if (g4 > 0) {
            float i13p = i13s[(g4 - 1) * 256 + x];
            float i14p = i14s[(g4 - 1) * 256 + x];
            float Tp   = Tsm[(g4 * 4 - 1) * 256 + x];
            h3 = __fadd_rn(Cprev, i13p);           // cs[64g4-3]
            h2 = __fadd_rn(Cprev, i14p);           // cs[64g4-2]
            h1 = __fadd_rn(Cprev, Tp);             // cs[64g4-1]
        }
        float Cm = C;
        #pragma unroll
        for (int m = 0; m < 4; m++) {
            int base = g4 * 64 + m * 16;
            float inner = 0.f;
            #pragma unroll
            for (int j = 0; j < 16; j++) {
                int t = base + j;
                float v = pA[t * LW];
                if (pB) v = __fmul_rn(v, pB[t * LW]);
                inner = __fadd_rn(inner, v);
                float cs = __fadd_rn(Cm, inner);
                if (t >= 1) {
                    float ov = (t >= 3) ? __fsub_rn(cs, h3) : cs;
                    pp[(t - 1) * LW + x] = ov;
                }
                h3 = h2; h2 = h1; h1 = cs;
            }
            Cm = __fadd_rn(Cm, Tloc[m]);
        }
        if (g4 == 3) pp[(LH - 1) * LW + x] = __fsub_rn(h1, h3);
    }
    __syncthreads();

    // ---- Phase 2: horizontal scan + diff, warps 0..15, 8 passes ----
    if (tid < 512) {
        int wid = tid >> 5;
        int lane = tid & 31;
        int half = (lane >> 4) & 1;
        int k = lane & 15;
        float* rowbuf = smem_pool;      // reuse as [32][256]

        for (int pass = 0; pass < 8; pass++) {
            int y = (pass * 16 + wid) * 2 + half;
            const float4* rv = (const float4*)(pp + (size_t)y * LW) + k * 4;
            float4 a0 = rv[0], a1 = rv[1], a2 = rv[2], a3 = rv[3];
            float e[16] = {a0.x, a0.y, a0.z, a0.w,
                           a1.x, a1.y, a1.z, a1.w,
                           a2.x, a2.y, a2.z, a2.w,
                           a3.x, a3.y, a3.z, a3.w};
            float pre[16];
            pre[0] = e[0];
            #pragma unroll
            for (int j = 1; j < 16; j++) pre[j] = __fadd_rn(pre[j - 1], e[j]);

            float T = pre[15];
            float carry = 0.f;
            #pragma unroll
            for (int i = 0; i < 16; i++) {
                float Ti = __shfl_sync(0xFFFFFFFFu, T, (half << 4) | i);
                if (i < k) carry = __fadd_rn(carry, Ti);   // serial fold
            }

            float* rb = rowbuf + (wid * 2 + half) * 256;
            #pragma unroll
            for (int j = 0; j < 16; j++)
                rb[k * 16 + j] = __fadd_rn(carry, pre[j]);
            __syncwarp();

            #pragma unroll
            for (int h = 0; h < 2; h++) {
                int yy = (pass * 16 + wid) * 2 + h;
                const float* rr = rowbuf + (wid * 2 + h) * 256;
                float* orow = pp + (size_t)yy * LW;
                #pragma unroll
                for (int j = 0; j < 8; j++) {
                    int i = j * 32 + lane;
                    float ov;
                    if (i == 0)            ov = rr[1];
                    else if (i == 1)       ov = rr[2];
                    else if (i == LW - 1)  ov = __fsub_rn(rr[LW - 1], rr[LW - 3]);
                    else                   ov = __fsub_rn(rr[i + 1], rr[i - 2]);
                    orow[i] = ov;
                }
            }
            __syncwarp();
        }
    }
}

// ---------------------------------------------------------------------------
// Kernel 2: per-pixel covariance solve -> pixel-major A/b (float4 stores)
// ---------------------------------------------------------------------------
__global__ void __launch_bounds__(256) gf_solve()
{
    int idx = blockIdx.x * blockDim.x + threadIdx.x;
    if (idx >= NB * PL) return;
    int x = idx % LW;
    int y = (idx / LW) % LH;
    int b = idx / PL;

    const float* box = g_box + (size_t)b * NPL * PL + y * LW + x;

    int y0 = max(0, y - 1), y1 = min(LH - 1, y + 1);
    int x0 = max(0, x - 1), x1 = min(LW - 1, x + 1);
    float n = (float)((y1 - y0 + 1) * (x1 - x0 + 1));

    float mx[3], my[3];
    #pragma unroll
    for (int c = 0; c < 3; c++) mx[c] = __fdiv_rn(box[c * PL], n);
    #pragma unroll
    for (int c = 0; c < 3; c++) my[c] = __fdiv_rn(box[(3 + c) * PL], n);

    float v[6];
    {
        const int i1[6] = {0, 0, 0, 1, 1, 2};
        const int i2[6] = {0, 1, 2, 1, 2, 2};
        #pragma unroll
        for (int k = 0; k < 6; k++) {
            float d = __fdiv_rn(box[(6 + k) * PL], n);
            float mm = __fmul_rn(mx[i1[k]], mx[i2[k]]);
            v[k] = __fadd_rn(__fsub_rn(d, mm), EPSV);
        }
    }

    float c0 = __fsub_rn(__fmul_rn(v[3], v[5]), __fmul_rn(v[4], v[4]));
    float c1 = __fsub_rn(__fmul_rn(v[4], v[2]), __fmul_rn(v[1], v[5]));
    float c2 = __fsub_rn(__fmul_rn(v[1], v[4]), __fmul_rn(v[3], v[2]));
    float c3 = __fsub_rn(__fmul_rn(v[0], v[5]), __fmul_rn(v[2], v[2]));
    float c4 = __fsub_rn(__fmul_rn(v[2], v[1]), __fmul_rn(v[0], v[4]));
    float c5 = __fsub_rn(__fmul_rn(v[0], v[3]), __fmul_rn(v[1], v[1]));

    float det = __fadd_rn(__fadd_rn(__fmul_rn(c0, v[0]), __fmul_rn(c1, v[1])),
                          __fmul_rn(c2, v[2]));
    c0 = __fdiv_rn(c0, det);
    c1 = __fdiv_rn(c1, det);
    c2 = __fdiv_rn(c2, det);
    c3 = __fdiv_rn(c3, det);
    c4 = __fdiv_rn(c4, det);
    c5 = __fdiv_rn(c5, det);

    float4* o4 = (float4*)(g_ab2 + ((size_t)b * PL + (size_t)y * LW + x) * 12);

    #pragma unroll
    for (int i = 0; i < 3; i++) {
        float cov[3];
        #pragma unroll
        for (int c = 0; c < 3; c++) {
            float d = __fdiv_rn(box[(12 + i * 3 + c) * PL], n);
            cov[c] = __fsub_rn(d, __fmul_rn(mx[c], my[i]));
        }
        float A0 = __fadd_rn(__fadd_rn(__fmul_rn(c0, cov[0]), __fmul_rn(c1, cov[1])),
                             __fmul_rn(c2, cov[2]));
        float A1 = __fadd_rn(__fadd_rn(__fmul_rn(c1, cov[0]), __fmul_rn(c3, cov[1])),
                             __fmul_rn(c4, cov[2]));
        float A2 = __fadd_rn(__fadd_rn(__fmul_rn(c2, cov[0]), __fmul_rn(c4, cov[1])),
                             __fmul_rn(c5, cov[2]));
        float s = __fadd_rn(__fadd_rn(__fmul_rn(A0, mx[0]), __fmul_rn(A1, mx[1])),
                            __fmul_rn(A2, mx[2]));
        float bb = __fsub_rn(my[i], s);
        o4[i] = make_float4(A0, A1, A2, bb);
    }
}

// ---------------------------------------------------------------------------
// Kernel 3: bilinear upsample + apply. Thread = 4 consecutive output x.
// ---------------------------------------------------------------------------
__global__ void __launch_bounds__(256) gf_apply(
    const float* __restrict__ hrx,
    float* __restrict__ out)
{
    int idx = blockIdx.x * blockDim.x + threadIdx.x;   // NB*HH*256
    int g = idx & 255;
    int y = (idx >> 8) & (HH - 1);
    int b = idx >> 18;

    float fy = (y + 0.5f) * 0.25f - 0.5f;
    fy = fminf(fmaxf(fy, 0.0f), (float)(LH - 1));
    int iy0 = (int)fy;
    float wy = fy - (float)iy0;
    int iy1 = min(iy0 + 1, LH - 1);
    float wy0 = 1.0f - wy, wy1 = wy;

    int colA = max(g - 1, 0);
    int colC = min(g + 1, LW - 1);

    const float4* ab = (const float4*)g_ab2 + (size_t)b * PL * 3;
    float4 cvA[3], cvB[3], cvC[3];
    {
        int cols[3] = {colA, g, colC};
        #pragma unroll
        for (int c = 0; c < 3; c++) {
            const float4* top = ab + ((size_t)iy0 * LW + cols[c]) * 3;
            const float4* bot = ab + ((size_t)iy1 * LW + cols[c]) * 3;
            float4* dst = (c == 0) ? cvA : (c == 1) ? cvB : cvC;
            #pragma unroll
            for (int q = 0; q < 3; q++) {
                float4 t = top[q], bo = bot[q];
                float4 r;
                r.x = __fadd_rn(__fmul_rn(t.x, wy0), __fmul_rn(bo.x, wy1));
                r.y = __fadd_rn(__fmul_rn(t.y, wy0), __fmul_rn(bo.y, wy1));
                r.z = __fadd_rn(__fmul_rn(t.z, wy0), __fmul_rn(bo.z, wy1));
                r.w = __fadd_rn(__fmul_rn(t.w, wy0), __fmul_rn(bo.w, wy1));
                dst[q] = r;
            }
        }
    }

    size_t hbase = (((size_t)b * 3) * HH + y) * HW + ((size_t)g << 2);
    const size_t hpl = (size_t)HH * HW;
    float4 hq0 = *(const float4*)(hrx + hbase);
    float4 hq1 = *(const float4*)(hrx + hbase + hpl);
    float4 hq2 = *(const float4*)(hrx + hbase + 2 * hpl);
    float hx0[4] = {hq0.x, hq0.y, hq0.z, hq0.w};
    float hx1[4] = {hq1.x, hq1.y, hq1.z, hq1.w};
    float hx2[4] = {hq2.x, hq2.y, hq2.z, hq2.w};

    float o0[4], o1[4], o2[4];
    #pragma unroll
    for (int d = 0; d < 4; d++) {
        float fx = ((float)(4 * g + d) + 0.5f) * 0.25f - 0.5f;
        fx = fminf(fmaxf(fx, 0.0f), (float)(LW - 1));
        int ix0 = (int)fx;
        float wx = fx - (float)ix0;
        int ix1 = min(ix0 + 1, LW - 1);
        float wx0 = 1.0f - wx, wx1 = wx;
        int i0 = ix0 - g + 1;
        int i1 = ix1 - g + 1;

        #pragma unroll
        for (int q = 0; q < 3; q++) {
            float4 l = (i0 == 0) ? cvA[q] : cvB[q];
            float4 rr = (i1 == 2) ? cvC[q] : cvB[q];
            float v0 = __fadd_rn(__fmul_rn(l.x, wx0), __fmul_rn(rr.x, wx1));
            float v1 = __fadd_rn(__fmul_rn(l.y, wx0), __fmul_rn(rr.y, wx1));
            float v2 = __fadd_rn(__fmul_rn(l.z, wx0), __fmul_rn(rr.z, wx1));
            float v3 = __fadd_rn(__fmul_rn(l.w, wx0), __fmul_rn(rr.w, wx1));
            float s = __fadd_rn(__fadd_rn(__fmul_rn(v0, hx0[d]),
                                          __fmul_rn(v1, hx1[d])),
                                __fmul_rn(v2, hx2[d]));
            float oo = __fadd_rn(s, v3);
            if (q == 0) o0[d] = oo; else if (q == 1) o1[d] = oo; else o2[d] = oo;
        }
    }

    float* outp = out + hbase;
    *(float4*)outp = make_float4(o0[0], o0[1], o0[2], o0[3]);
    *(float4*)(outp + hpl) = make_float4(o1[0], o1[1], o1[2], o1[3]);
    *(float4*)(outp + 2 * hpl) = make_float4(o2[0], o2[1], o2[2], o2[3]);
}

extern "C" void kernel_launch(void* const* d_in, const int* in_sizes, int n_in,
                              void* d_out, int out_size)
{
    const float* lrx = (const float*)d_in[0];
    const float* lry = (const float*)d_in[1];
    const float* hrx = (const float*)d_in[2];
    float* out = (float*)d_out;

    gf_box<<<NB * NPL, 1024>>>(lrx, lry);                          // 168 blocks
    gf_solve<<<(NB * PL + 255) / 256, 256>>>();                    // 2048 blocks
    gf_apply<<<(NB * HH * (HW / 4) + 255) / 256, 256>>>(hrx, out); // 8192 blocks
}